// round 9
// baseline (speedup 1.0000x reference)
#include <cuda_runtime.h>
#include <cuda_fp16.h>
#include <cuda_bf16.h>
#include <cstdint>

// Problem constants
#define TT 256
#define BB 1024
#define OBS 128
#define LS 128
#define HH 128
#define NA 18
#define MROWS (TT*BB)          // 262144

// ---------------------------------------------------------------------------
// Scratch (device globals; no cudaMalloc allowed)
// ---------------------------------------------------------------------------
__device__ float g_h1[(size_t)MROWS * 128];   // encoder layer-1 out
__device__ float g_h2[(size_t)MROWS * 32];    // encoder layer-2 out
__device__ float g_h3[(size_t)MROWS * 128];   // encoder layer-3 out
__device__ float g_Z [(size_t)MROWS * 512];   // precomputed input gates + biases

// bf16 hi/lo weight limbs: W1(16384) | W2(4096) | W3(4096) | Wih(65536)
#define WOFF_W1  0
#define WOFF_W2  16384
#define WOFF_W3  20480
#define WOFF_WIH 24576
#define WTOT     90112
__device__ __nv_bfloat16 g_Wbh[WTOT];
__device__ __nv_bfloat16 g_Wbl[WTOT];

// ---------------------------------------------------------------------------
// Helpers
// ---------------------------------------------------------------------------
__device__ __forceinline__ uint32_t smem_u32(const void* p) {
    uint32_t a;
    asm("{ .reg .u64 t; cvta.to.shared.u64 t, %1; cvt.u32.u64 %0, t; }"
        : "=r"(a) : "l"(p));
    return a;
}
__device__ __forceinline__ uint32_t bpack(__nv_bfloat16 a, __nv_bfloat16 b) {
    __nv_bfloat162 t{a, b};
    return *reinterpret_cast<uint32_t*>(&t);
}

#define LDSM_X4(r0, r1, r2, r3, addr) \
    asm volatile("ldmatrix.sync.aligned.m8n8.x4.shared.b16 {%0,%1,%2,%3}, [%4];" \
                 : "=r"(r0), "=r"(r1), "=r"(r2), "=r"(r3) : "r"(addr))

__device__ __forceinline__ void mma16816(float* d, const uint32_t* a,
                                         uint32_t b0, uint32_t b1) {
    asm volatile(
        "mma.sync.aligned.m16n8k16.row.col.f32.bf16.bf16.f32 "
        "{%0,%1,%2,%3}, {%4,%5,%6,%7}, {%8,%9}, {%0,%1,%2,%3};"
        : "+f"(d[0]), "+f"(d[1]), "+f"(d[2]), "+f"(d[3])
        : "r"(a[0]), "r"(a[1]), "r"(a[2]), "r"(a[3]), "r"(b0), "r"(b1));
}

// ---------------------------------------------------------------------------
// Weight conversion: fp32 -> bf16 hi/lo limbs (runs once per launch; tiny)
// ---------------------------------------------------------------------------
__global__ void convw_kernel(const float* __restrict__ src,
                             __nv_bfloat16* __restrict__ dh,
                             __nv_bfloat16* __restrict__ dl, int n) {
    for (int i = blockIdx.x * blockDim.x + threadIdx.x; i < n;
         i += gridDim.x * blockDim.x) {
        float v = src[i];
        __nv_bfloat16 h = __float2bfloat16_rn(v);
        dh[i] = h;
        dl[i] = __float2bfloat16_rn(v - __bfloat162float(h));
    }
}

// ---------------------------------------------------------------------------
// Tensor-core GEMM via mma.sync (bf16 3-limb split, fp32 accumulate)
//   C[M][N] = act( A[M][K] @ W[N][K]^T + bias1 (+ bias2) )
// CTA: 256 threads = 8 warps (4M x 2N), tile 128 x 64, N looped in 64-chunks.
// ---------------------------------------------------------------------------
template<int K, bool RELU>
__global__ void __launch_bounds__(256) gemm_mma(
    const float* __restrict__ A,
    const __nv_bfloat16* __restrict__ Wh, const __nv_bfloat16* __restrict__ Wl,
    const float* __restrict__ bias1, const float* __restrict__ bias2,
    float* __restrict__ C, int N)
{
    constexpr int SA = K + 8;          // padded row stride (bf16 elems)
    constexpr int KSTEPS = K / 16;

    extern __shared__ char sm[];
    __nv_bfloat16* Ash = reinterpret_cast<__nv_bfloat16*>(sm);
    __nv_bfloat16* Asl = Ash + 128 * SA;
    __nv_bfloat16* Bsh = Asl + 128 * SA;
    __nv_bfloat16* Bsl = Bsh + 64 * SA;

    const int tid  = threadIdx.x;
    const long row0 = (long)blockIdx.x * 128;

    // ---- Stage + split A tile (once per CTA) ----
    for (int idx = tid; idx < 128 * (K / 4); idx += 256) {
        int row = idx / (K / 4), col = (idx % (K / 4)) * 4;
        float4 v = *reinterpret_cast<const float4*>(A + (row0 + row) * K + col);
        __nv_bfloat16 h0 = __float2bfloat16_rn(v.x);
        __nv_bfloat16 h1 = __float2bfloat16_rn(v.y);
        __nv_bfloat16 h2 = __float2bfloat16_rn(v.z);
        __nv_bfloat16 h3 = __float2bfloat16_rn(v.w);
        __nv_bfloat16 l0 = __float2bfloat16_rn(v.x - __bfloat162float(h0));
        __nv_bfloat16 l1 = __float2bfloat16_rn(v.y - __bfloat162float(h1));
        __nv_bfloat16 l2 = __float2bfloat16_rn(v.z - __bfloat162float(h2));
        __nv_bfloat16 l3 = __float2bfloat16_rn(v.w - __bfloat162float(h3));
        uint2 uh{bpack(h0, h1), bpack(h2, h3)};
        uint2 ul{bpack(l0, l1), bpack(l2, l3)};
        *reinterpret_cast<uint2*>(Ash + row * SA + col) = uh;
        *reinterpret_cast<uint2*>(Asl + row * SA + col) = ul;
    }

    // ---- Per-warp fragment addressing ----
    const int wid  = tid >> 5, lane = tid & 31;
    const int warp_m = (wid >> 1) * 32;   // 4 M-warps
    const int warp_n = (wid & 1) * 32;    // 2 N-warps
    const int grp  = lane >> 2, tig = lane & 3;
    const int lrow = lane & 15;
    const int lk   = (lane >> 4) * 8;

    uint32_t aAh[2], aAl[2], aBh[2], aBl[2];
    #pragma unroll
    for (int i = 0; i < 2; ++i) {
        aAh[i] = smem_u32(Ash + (warp_m + 16 * i + lrow) * SA + lk);
        aAl[i] = smem_u32(Asl + (warp_m + 16 * i + lrow) * SA + lk);
    }
    #pragma unroll
    for (int j2 = 0; j2 < 2; ++j2) {
        aBh[j2] = smem_u32(Bsh + (warp_n + 16 * j2 + lrow) * SA + lk);
        aBl[j2] = smem_u32(Bsl + (warp_n + 16 * j2 + lrow) * SA + lk);
    }

    for (int c0 = 0; c0 < N; c0 += 64) {
        // ---- Stage B tile (bf16 limbs from precomputed weights) ----
        for (int idx = tid; idx < 64 * (K / 8); idx += 256) {
            int row = idx / (K / 8), c8 = (idx % (K / 8)) * 8;
            int n = c0 + row;
            uint4 vh{0, 0, 0, 0}, vl{0, 0, 0, 0};
            if (n < N) {
                vh = *reinterpret_cast<const uint4*>(Wh + (long)n * K + c8);
                vl = *reinterpret_cast<const uint4*>(Wl + (long)n * K + c8);
            }
            *reinterpret_cast<uint4*>(Bsh + row * SA + c8) = vh;
            *reinterpret_cast<uint4*>(Bsl + row * SA + c8) = vl;
        }
        __syncthreads();

        float acc[2][4][4];
        #pragma unroll
        for (int i = 0; i < 2; ++i)
            #pragma unroll
            for (int j = 0; j < 4; ++j)
                #pragma unroll
                for (int e = 0; e < 4; ++e) acc[i][j][e] = 0.f;

        #pragma unroll
        for (int ks = 0; ks < KSTEPS; ++ks) {
            const uint32_t kb = ks * 32;   // 16 bf16 = 32 bytes per k-step
            uint32_t af[2][2][4];          // [limb][atom_i][4]
            #pragma unroll
            for (int i = 0; i < 2; ++i) {
                LDSM_X4(af[0][i][0], af[0][i][1], af[0][i][2], af[0][i][3], aAh[i] + kb);
                LDSM_X4(af[1][i][0], af[1][i][1], af[1][i][2], af[1][i][3], aAl[i] + kb);
            }
            uint32_t bf_[2][2][4];         // [limb][j2][4]
            #pragma unroll
            for (int j2 = 0; j2 < 2; ++j2) {
                LDSM_X4(bf_[0][j2][0], bf_[0][j2][1], bf_[0][j2][2], bf_[0][j2][3], aBh[j2] + kb);
                LDSM_X4(bf_[1][j2][0], bf_[1][j2][1], bf_[1][j2][2], bf_[1][j2][3], aBl[j2] + kb);
            }
            #pragma unroll
            for (int i = 0; i < 2; ++i)
                #pragma unroll
                for (int j = 0; j < 4; ++j) {
                    const int j2 = j >> 1, s = j & 1;
                    mma16816(acc[i][j], af[0][i], bf_[0][j2][s], bf_[0][j2][2 + s]); // Ah*Wh
                    mma16816(acc[i][j], af[0][i], bf_[1][j2][s], bf_[1][j2][2 + s]); // Ah*Wl
                    mma16816(acc[i][j], af[1][i], bf_[0][j2][s], bf_[0][j2][2 + s]); // Al*Wh
                }
        }
        __syncthreads();   // Bs free for next tile

        // ---- Epilogue ----
        #pragma unroll
        for (int i = 0; i < 2; ++i) {
            const long r0 = row0 + warp_m + 16 * i + grp;
            #pragma unroll
            for (int j = 0; j < 4; ++j) {
                const int col = c0 + warp_n + 8 * j + 2 * tig;
                if (col < N) {
                    float2 bb = *reinterpret_cast<const float2*>(bias1 + col);
                    if (bias2) {
                        float2 b2 = *reinterpret_cast<const float2*>(bias2 + col);
                        bb.x += b2.x; bb.y += b2.y;
                    }
                    float2 o0{acc[i][j][0] + bb.x, acc[i][j][1] + bb.y};
                    float2 o1{acc[i][j][2] + bb.x, acc[i][j][3] + bb.y};
                    if (RELU) {
                        o0.x = fmaxf(o0.x, 0.f); o0.y = fmaxf(o0.y, 0.f);
                        o1.x = fmaxf(o1.x, 0.f); o1.y = fmaxf(o1.y, 0.f);
                    }
                    *reinterpret_cast<float2*>(C + r0 * N + col) = o0;
                    *reinterpret_cast<float2*>(C + (r0 + 8) * N + col) = o1;
                }
            }
        }
    }
}

// ---------------------------------------------------------------------------
// Fast nonlinearities (MUFU; fma pipe stays free for the matvec)
// ---------------------------------------------------------------------------
__device__ __forceinline__ float sigm_fast(float x) {
    x = fminf(fmaxf(x, -30.f), 30.f);
    return __fdividef(1.f, 1.f + __expf(-x));
}
__device__ __forceinline__ float tanh_fast(float x) {
    x = fminf(fmaxf(x, -15.f), 15.f);
    float e = __expf(-2.f * x);
    return __fdividef(1.f - e, 1.f + e);
}

// ---------------------------------------------------------------------------
// Persistent LSTM recurrence + heads (unchanged; proven at ~1.6ms / 1e-4)
// ---------------------------------------------------------------------------
#define OFF_WSH   0
#define OFF_HBUF  131072
#define OFF_CBUF  134656
#define OFF_GBUF  138240
#define OFF_WAC   154624
#define OFF_BAC   164672
#define OFF_MS    164752
#define SMEM_LSTM 164784

__global__ void __launch_bounds__(512, 1) lstm_kernel(
    const float* __restrict__ Z,    const float* __restrict__ done,
    const float* __restrict__ h0,   const float* __restrict__ c0,
    const float* __restrict__ Whh,
    const float* __restrict__ Wa,   const float* __restrict__ ba,
    const float* __restrict__ Wc,   const float* __restrict__ bc,
    float* __restrict__ out)
{
    extern __shared__ char smraw[];
    __half* wsh  = reinterpret_cast<__half*>(smraw + OFF_WSH);
    float*  hbuf = reinterpret_cast<float*>(smraw + OFF_HBUF);
    float*  cbuf = reinterpret_cast<float*>(smraw + OFF_CBUF);
    float*  gbuf = reinterpret_cast<float*>(smraw + OFF_GBUF);
    float*  WaCs = reinterpret_cast<float*>(smraw + OFF_WAC);
    float*  bac  = reinterpret_cast<float*>(smraw + OFF_BAC);
    float*  ms   = reinterpret_cast<float*>(smraw + OFF_MS);

    const int tid = threadIdx.x;
    const int cta = blockIdx.x;
    const int gb0 = (cta < 136) ? cta * 7 : 952 + (cta - 136) * 6;
    const int nb  = (cta < 136) ? 7 : 6;

    for (int idx = tid; idx < 512 * 128; idx += 512) {
        int jj = idx >> 7, k = idx & 127;
        wsh[((k >> 2) << 11) + (jj << 2) + (k & 3)] = __float2half(Whh[idx]);
    }
    for (int idx = tid; idx < 7 * 128; idx += 512) {
        int b = idx >> 7, u = idx & 127;
        hbuf[idx] = (b < nb) ? h0[(gb0 + b) * HH + u] : 0.f;
        cbuf[idx] = (b < nb) ? c0[(gb0 + b) * HH + u] : 0.f;
    }
    for (int idx = tid; idx < 19 * 128; idx += 512) {
        int a = idx >> 7, k = idx & 127;
        WaCs[a * 132 + k] = (a < 18) ? Wa[a * 128 + k] : Wc[k];
    }
    if (tid < 19) bac[tid] = (tid < 18) ? ba[tid] : bc[0];
    if (tid < 7)  ms[tid]  = (tid < nb) ? (1.f - done[gb0 + tid]) : 1.f;
    __syncthreads();

    const int j    = tid;
    const int type = j >> 7;

    for (int t = 0; t < TT; ++t) {
        for (int idx = tid; idx < nb * 128; idx += 512) {
            float m = ms[idx >> 7];
            hbuf[idx] *= m;
            cbuf[idx] *= m;
        }
        __syncthreads();

        float zr[7];
        const long zbase = ((long)t * BB + gb0) * 512 + j;
        #pragma unroll
        for (int b = 0; b < 7; ++b)
            zr[b] = (b < nb) ? Z[zbase + (long)b * 512] : 0.f;
        float dn = 0.f;
        if (tid < 7)
            dn = (tid < nb && t < TT - 1) ? done[(t + 1) * BB + gb0 + tid] : 0.f;

        float acc[7] = {0.f, 0.f, 0.f, 0.f, 0.f, 0.f, 0.f};
        #pragma unroll 4
        for (int k4 = 0; k4 < 32; ++k4) {
            uint2 wr = *reinterpret_cast<const uint2*>(wsh + (k4 << 11) + (j << 2));
            float2 w01 = __half22float2(*reinterpret_cast<const __half2*>(&wr.x));
            float2 w23 = __half22float2(*reinterpret_cast<const __half2*>(&wr.y));
            #pragma unroll
            for (int b = 0; b < 7; ++b) {
                float4 hv = *reinterpret_cast<const float4*>(&hbuf[b * 128 + (k4 << 2)]);
                acc[b] = fmaf(w01.x, hv.x, acc[b]);
                acc[b] = fmaf(w01.y, hv.y, acc[b]);
                acc[b] = fmaf(w23.x, hv.z, acc[b]);
                acc[b] = fmaf(w23.y, hv.w, acc[b]);
            }
        }
        #pragma unroll
        for (int b = 0; b < 7; ++b) {
            float v = acc[b] + zr[b];
            float gv = (type == 2) ? tanh_fast(v) : sigm_fast(v);
            gbuf[(j << 3) + b] = gv;
        }
        if (tid < 7) ms[tid] = 1.f - dn;
        __syncthreads();

        for (int idx = tid; idx < nb * 128; idx += 512) {
            int u = idx & 127;
            int g8 = (u << 3) + (idx >> 7);
            float iv = gbuf[g8];
            float fv = gbuf[g8 + 1024];
            float gg = gbuf[g8 + 2048];
            float ov = gbuf[g8 + 3072];
            float cv = fmaf(fv, cbuf[idx], iv * gg);
            float hv = ov * tanh_fast(cv);
            cbuf[idx] = cv;
            hbuf[idx] = hv;
        }
        __syncthreads();

        if (tid < nb * 19) {
            int b = tid / 19, a = tid - b * 19;
            float s0 = 0.f, s1 = 0.f;
            #pragma unroll 4
            for (int k8 = 0; k8 < 16; ++k8) {
                float4 w0 = *reinterpret_cast<const float4*>(&WaCs[a * 132 + k8 * 8]);
                float4 w1 = *reinterpret_cast<const float4*>(&WaCs[a * 132 + k8 * 8 + 4]);
                float4 h0v = *reinterpret_cast<const float4*>(&hbuf[b * 128 + k8 * 8]);
                float4 h1v = *reinterpret_cast<const float4*>(&hbuf[b * 128 + k8 * 8 + 4]);
                s0 = fmaf(w0.x, h0v.x, s0); s0 = fmaf(w0.y, h0v.y, s0);
                s0 = fmaf(w0.z, h0v.z, s0); s0 = fmaf(w0.w, h0v.w, s0);
                s1 = fmaf(w1.x, h1v.x, s1); s1 = fmaf(w1.y, h1v.y, s1);
                s1 = fmaf(w1.z, h1v.z, s1); s1 = fmaf(w1.w, h1v.w, s1);
            }
            out[((long)t * BB + gb0 + b) * 19 + a] = s0 + s1 + bac[a];
        }
        __syncthreads();
    }
}

// ---------------------------------------------------------------------------
// Host launcher
// ---------------------------------------------------------------------------
extern "C" void kernel_launch(void* const* d_in, const int* in_sizes, int n_in,
                              void* d_out, int out_size)
{
    const float* x    = (const float*)d_in[0];
    const float* done = (const float*)d_in[1];
    const float* h0   = (const float*)d_in[2];
    const float* c0   = (const float*)d_in[3];
    const float* W1   = (const float*)d_in[4];
    const float* b1   = (const float*)d_in[5];
    const float* W2   = (const float*)d_in[6];
    const float* b2   = (const float*)d_in[7];
    const float* W3   = (const float*)d_in[8];
    const float* b3   = (const float*)d_in[9];
    const float* Wih  = (const float*)d_in[10];
    const float* Whh  = (const float*)d_in[11];
    const float* bih  = (const float*)d_in[12];
    const float* bhh  = (const float*)d_in[13];
    const float* Wa   = (const float*)d_in[14];
    const float* ba   = (const float*)d_in[15];
    const float* Wc   = (const float*)d_in[16];
    const float* bc   = (const float*)d_in[17];
    float* out = (float*)d_out;

    float *h1p, *h2p, *h3p, *Zp;
    __nv_bfloat16 *wbh, *wbl;
    cudaGetSymbolAddress((void**)&h1p, g_h1);
    cudaGetSymbolAddress((void**)&h2p, g_h2);
    cudaGetSymbolAddress((void**)&h3p, g_h3);
    cudaGetSymbolAddress((void**)&Zp,  g_Z);
    cudaGetSymbolAddress((void**)&wbh, g_Wbh);
    cudaGetSymbolAddress((void**)&wbl, g_Wbl);

    // Convert weights to bf16 hi/lo limbs (tiny)
    convw_kernel<<<64, 256>>>(W1,  wbh + WOFF_W1,  wbl + WOFF_W1,  16384);
    convw_kernel<<<16, 256>>>(W2,  wbh + WOFF_W2,  wbl + WOFF_W2,  4096);
    convw_kernel<<<16, 256>>>(W3,  wbh + WOFF_W3,  wbl + WOFF_W3,  4096);
    convw_kernel<<<256, 256>>>(Wih, wbh + WOFF_WIH, wbl + WOFF_WIH, 65536);

    // smem: (2*128 + 2*64) rows * (K+8) bf16 = 768*(K+8) bytes
    const int S_K128 = 768 * 136;  // 104448
    const int S_K32  = 768 * 40;   // 30720

    cudaFuncSetAttribute(gemm_mma<128, true>,
                         cudaFuncAttributeMaxDynamicSharedMemorySize, S_K128);
    cudaFuncSetAttribute(gemm_mma<128, false>,
                         cudaFuncAttributeMaxDynamicSharedMemorySize, S_K128);
    cudaFuncSetAttribute(gemm_mma<32, true>,
                         cudaFuncAttributeMaxDynamicSharedMemorySize, S_K32);
    cudaFuncSetAttribute(lstm_kernel,
                         cudaFuncAttributeMaxDynamicSharedMemorySize, SMEM_LSTM);

    const int NB = MROWS / 128;  // 2048 CTAs

    gemm_mma<128, true><<<NB, 256, S_K128>>>(
        x,   wbh + WOFF_W1,  wbl + WOFF_W1,  b1, nullptr, h1p, 128);
    gemm_mma<128, true><<<NB, 256, S_K128>>>(
        h1p, wbh + WOFF_W2,  wbl + WOFF_W2,  b2, nullptr, h2p, 32);
    gemm_mma<32, true><<<NB, 256, S_K32>>>(
        h2p, wbh + WOFF_W3,  wbl + WOFF_W3,  b3, nullptr, h3p, 128);
    gemm_mma<128, false><<<NB, 256, S_K128>>>(
        h3p, wbh + WOFF_WIH, wbl + WOFF_WIH, bih, bhh, Zp, 512);

    // Recurrence + heads
    lstm_kernel<<<148, 512, SMEM_LSTM>>>(
        Zp, done, h0, c0, Whh, Wa, ba, Wc, bc, out);
}

// round 10
// speedup vs baseline: 1.2288x; 1.2288x over previous
#include <cuda_runtime.h>
#include <cuda_fp16.h>
#include <cuda_bf16.h>
#include <cstdint>

// Problem constants
#define TT 256
#define BB 1024
#define OBS 128
#define LS 128
#define HH 128
#define NA 18
#define MROWS (TT*BB)          // 262144

// ---------------------------------------------------------------------------
// Scratch (device globals; no cudaMalloc allowed)
// ---------------------------------------------------------------------------
__device__ float g_h1[(size_t)MROWS * 128];   // encoder layer-1 out
__device__ float g_h2[(size_t)MROWS * 32];    // encoder layer-2 out
__device__ float g_h3[(size_t)MROWS * 128];   // encoder layer-3 out
__device__ float g_Z [(size_t)MROWS * 512];   // precomputed input gates + biases

// ---------------------------------------------------------------------------
// f32x2 packed-FMA helpers (sm_100+ base PTX; 2x fp32 MAC rate, exact fp32)
// ---------------------------------------------------------------------------
__device__ __forceinline__ void ffma2(uint64_t& acc, uint64_t a, uint64_t b) {
    asm("fma.rn.f32x2 %0, %1, %2, %0;" : "+l"(acc) : "l"(a), "l"(b));
}
__device__ __forceinline__ uint64_t pack2(float x, float y) {
    uint64_t r;
    asm("mov.b64 %0, {%1, %2};" : "=l"(r) : "f"(x), "f"(y));
    return r;
}
__device__ __forceinline__ void unpack2(uint64_t v, float& lo, float& hi) {
    asm("mov.b64 {%0, %1}, %2;" : "=f"(lo), "=f"(hi) : "l"(v));
}

// ---------------------------------------------------------------------------
// Fast nonlinearities (MUFU; fma pipe stays free)
// ---------------------------------------------------------------------------
__device__ __forceinline__ float sigm_fast(float x) {
    x = fminf(fmaxf(x, -30.f), 30.f);
    return __fdividef(1.f, 1.f + __expf(-x));
}
__device__ __forceinline__ float tanh_fast(float x) {
    x = fminf(fmaxf(x, -15.f), 15.f);
    float e = __expf(-2.f * x);
    return __fdividef(1.f - e, 1.f + e);
}

// ---------------------------------------------------------------------------
// Tiled SIMT GEMM on f32x2:  C[M][N] = act( A[M][K] @ W[N][K]^T + b1 (+b2) )
// Tile: 64 rows x NT cols, 256 threads, whole K in smem (proven R3 layout).
// Inner loop: packed fp32 FMA pairing output rows (exact fp32 math).
// ---------------------------------------------------------------------------
template<int KT, int NT, bool RELU>
__global__ void __launch_bounds__(256, 2) gemm_kernel(
    const float* __restrict__ A, const float* __restrict__ W,
    const float* __restrict__ bias1, const float* __restrict__ bias2,
    float* __restrict__ C, int N)
{
    constexpr int AP  = 68;        // padded leading dim for As[k][r]
    constexpr int BP  = NT + 4;    // padded leading dim for Bs[k][j]
    constexpr int KQ  = KT / 4;
    constexpr int CPT = NT / 32;   // cols per thread (4 or 1)

    extern __shared__ float smg[];
    float* As = smg;               // KT * AP
    float* Bs = smg + KT * AP;     // KT * BP

    const int  tid  = threadIdx.x;
    const long row0 = (long)blockIdx.x * 64;
    const int  c0   = blockIdx.y * NT;

    // Load A tile transposed (As[k][r])
    for (int idx = tid; idx < KQ * 64; idx += 256) {
        int kq = idx / 64, r = idx % 64;
        float4 v = *reinterpret_cast<const float4*>(A + (row0 + r) * KT + kq * 4);
        As[(kq*4+0)*AP + r] = v.x;
        As[(kq*4+1)*AP + r] = v.y;
        As[(kq*4+2)*AP + r] = v.z;
        As[(kq*4+3)*AP + r] = v.w;
    }
    // Load W tile transposed (Bs[k][j])
    for (int idx = tid; idx < KQ * NT; idx += 256) {
        int kq = idx / NT, jj = idx % NT;
        float4 v = *reinterpret_cast<const float4*>(W + (long)(c0 + jj) * KT + kq * 4);
        Bs[(kq*4+0)*BP + jj] = v.x;
        Bs[(kq*4+1)*BP + jj] = v.y;
        Bs[(kq*4+2)*BP + jj] = v.z;
        Bs[(kq*4+3)*BP + jj] = v.w;
    }
    __syncthreads();

    const int tx = tid & 31, ty = tid >> 5;
    uint64_t acc2[4][CPT];
    #pragma unroll
    for (int i2 = 0; i2 < 4; ++i2)
        #pragma unroll
        for (int c = 0; c < CPT; ++c) acc2[i2][c] = 0ull;

    #pragma unroll 8
    for (int k = 0; k < KT; ++k) {
        // A row-pairs come packed for free (16B-aligned adjacent rows)
        ulonglong2 av0 = *reinterpret_cast<const ulonglong2*>(&As[k * AP + ty * 8]);
        ulonglong2 av1 = *reinterpret_cast<const ulonglong2*>(&As[k * AP + ty * 8 + 4]);
        uint64_t ap[4] = {av0.x, av0.y, av1.x, av1.y};
        float bb[CPT];
        if constexpr (CPT == 4) {
            float4 bv = *reinterpret_cast<const float4*>(&Bs[k * BP + tx * 4]);
            bb[0] = bv.x; bb[1] = bv.y; bb[2] = bv.z; bb[3] = bv.w;
        } else {
            bb[0] = Bs[k * BP + tx];
        }
        #pragma unroll
        for (int c = 0; c < CPT; ++c) {
            uint64_t bd = pack2(bb[c], bb[c]);
            #pragma unroll
            for (int i2 = 0; i2 < 4; ++i2)
                ffma2(acc2[i2][c], ap[i2], bd);
        }
    }

    // Unpack into row-indexed accumulators
    float acc[8][CPT];
    #pragma unroll
    for (int i2 = 0; i2 < 4; ++i2)
        #pragma unroll
        for (int c = 0; c < CPT; ++c)
            unpack2(acc2[i2][c], acc[2*i2][c], acc[2*i2+1][c]);

    // Epilogue (unchanged from proven R3 kernel)
    if constexpr (CPT == 4) {
        float bsum[4];
        #pragma unroll
        for (int c = 0; c < 4; ++c) {
            int col = c0 + tx * 4 + c;
            bsum[c] = bias1[col] + (bias2 ? bias2[col] : 0.f);
        }
        #pragma unroll
        for (int i = 0; i < 8; ++i) {
            long row = row0 + ty * 8 + i;
            float4 o;
            o.x = acc[i][0] + bsum[0];
            o.y = acc[i][1] + bsum[1];
            o.z = acc[i][2] + bsum[2];
            o.w = acc[i][3] + bsum[3];
            if (RELU) {
                o.x = fmaxf(o.x, 0.f); o.y = fmaxf(o.y, 0.f);
                o.z = fmaxf(o.z, 0.f); o.w = fmaxf(o.w, 0.f);
            }
            *reinterpret_cast<float4*>(C + row * N + c0 + tx * 4) = o;
        }
    } else {
        int col = c0 + tx;
        float bsum = bias1[col] + (bias2 ? bias2[col] : 0.f);
        #pragma unroll
        for (int i = 0; i < 8; ++i) {
            long row = row0 + ty * 8 + i;
            float v = acc[i][0] + bsum;
            if (RELU) v = fmaxf(v, 0.f);
            C[row * N + col] = v;
        }
    }
}

// ---------------------------------------------------------------------------
// Persistent LSTM recurrence + heads, f32x2 matvec.
// 128 CTAs x 512 threads; each CTA owns 8 batch lanes (4 f32x2 pairs).
// Whh fp16 in smem (proven); h kept fp32 (pair-interleaved + per-lane).
// done-mask folded algebraically: acc*m and c*m (phase-1 eliminated).
// gbuf padded stride 9 (9 coprime 32 -> conflict-free).
// ---------------------------------------------------------------------------
#define OFF_WSH   0                         // 512*128 half   = 131072
#define OFF_HBUF  131072                    // 8*128 f32      =   4096
#define OFF_CBUF  135168                    //                =   4096
#define OFF_HP    139264                    // 4*128 float2   =   4096
#define OFF_GBUF  143360                    // 512*9 f32      =  18432
#define OFF_WAC   161792                    // 19*132 f32     =  10048 (pad)
#define OFF_BAC   171840                    // 19 f32         =     80 (pad)
#define OFF_MS    171920                    // 2*8 f32        =     64
#define SMEM_LSTM 171984

__global__ void __launch_bounds__(512, 1) lstm_kernel(
    const float* __restrict__ Z,    const float* __restrict__ done,
    const float* __restrict__ h0,   const float* __restrict__ c0,
    const float* __restrict__ Whh,
    const float* __restrict__ Wa,   const float* __restrict__ ba,
    const float* __restrict__ Wc,   const float* __restrict__ bc,
    float* __restrict__ out)
{
    extern __shared__ char smraw[];
    __half*  wsh  = reinterpret_cast<__half*>(smraw + OFF_WSH);
    float*   hbuf = reinterpret_cast<float*>(smraw + OFF_HBUF);
    float*   cbuf = reinterpret_cast<float*>(smraw + OFF_CBUF);
    float2*  hp   = reinterpret_cast<float2*>(smraw + OFF_HP);
    float*   gbuf = reinterpret_cast<float*>(smraw + OFF_GBUF);
    float*   WaCs = reinterpret_cast<float*>(smraw + OFF_WAC);
    float*   bac  = reinterpret_cast<float*>(smraw + OFF_BAC);
    float*   ms   = reinterpret_cast<float*>(smraw + OFF_MS);

    const int tid = threadIdx.x;
    const int gb0 = blockIdx.x * 8;        // 128 CTAs x 8 lanes = 1024

    // --- Whh -> fp16 smem, layout: element ((k>>2)<<11) + (j<<2) + (k&3)
    for (int idx = tid; idx < 512 * 128; idx += 512) {
        int jj = idx >> 7, k = idx & 127;
        wsh[((k >> 2) << 11) + (jj << 2) + (k & 3)] = __float2half(Whh[idx]);
    }
    // --- h0/c0 per-lane fp32
    for (int idx = tid; idx < 8 * 128; idx += 512) {
        int b = idx >> 7, u = idx & 127;
        hbuf[idx] = h0[(gb0 + b) * HH + u];
        cbuf[idx] = c0[(gb0 + b) * HH + u];
    }
    // --- h0 pair-interleaved for the f32x2 matvec
    for (int idx = tid; idx < 4 * 128; idx += 512) {
        int p = idx >> 7, k = idx & 127;
        hp[p * 128 + k] = make_float2(h0[(gb0 + 2*p) * HH + k],
                                      h0[(gb0 + 2*p + 1) * HH + k]);
    }
    // --- head weights (Wa rows 0..17, Wc row 18), ld=132
    for (int idx = tid; idx < 19 * 128; idx += 512) {
        int a = idx >> 7, k = idx & 127;
        WaCs[a * 132 + k] = (a < 18) ? Wa[a * 128 + k] : Wc[k];
    }
    if (tid < 19) bac[tid] = (tid < 18) ? ba[tid] : bc[0];
    if (tid < 8)  ms[tid]  = 1.f - done[gb0 + tid];   // slot 0 = mask for t=0
    __syncthreads();

    const int j    = tid;          // gate index 0..511
    const int type = j >> 7;       // 0=i,1=f,2=g,3=o (warp-uniform)

    for (int t = 0; t < TT; ++t) {
        const int slot  = (t & 1) * 8;
        const int nslot = ((t + 1) & 1) * 8;

        // ---- Phase A: gates = sigma( m_t * (Whh @ h) + Z ) ----
        float zr[8];
        const long zbase = ((long)t * BB + gb0) * 512 + j;
        #pragma unroll
        for (int b = 0; b < 8; ++b)
            zr[b] = Z[zbase + (long)b * 512];
        float dn = 0.f;
        if (tid < 8)
            dn = (t < TT - 1) ? done[(t + 1) * BB + gb0 + tid] : 0.f;
        float mk[8];
        #pragma unroll
        for (int b = 0; b < 8; ++b) mk[b] = ms[slot + b];

        uint64_t acc2[4] = {0ull, 0ull, 0ull, 0ull};
        #pragma unroll 4
        for (int k4 = 0; k4 < 32; ++k4) {
            uint2 wr = *reinterpret_cast<const uint2*>(wsh + (k4 << 11) + (j << 2));
            float2 w01 = __half22float2(*reinterpret_cast<const __half2*>(&wr.x));
            float2 w23 = __half22float2(*reinterpret_cast<const __half2*>(&wr.y));
            uint64_t wd0 = pack2(w01.x, w01.x);
            uint64_t wd1 = pack2(w01.y, w01.y);
            uint64_t wd2 = pack2(w23.x, w23.x);
            uint64_t wd3 = pack2(w23.y, w23.y);
            ulonglong2 ha[4], hb[4];
            #pragma unroll
            for (int p = 0; p < 4; ++p) {
                ha[p] = *reinterpret_cast<const ulonglong2*>(&hp[(p << 7) + (k4 << 2)]);
                hb[p] = *reinterpret_cast<const ulonglong2*>(&hp[(p << 7) + (k4 << 2) + 2]);
            }
            #pragma unroll
            for (int p = 0; p < 4; ++p) ffma2(acc2[p], wd0, ha[p].x);
            #pragma unroll
            for (int p = 0; p < 4; ++p) ffma2(acc2[p], wd1, ha[p].y);
            #pragma unroll
            for (int p = 0; p < 4; ++p) ffma2(acc2[p], wd2, hb[p].x);
            #pragma unroll
            for (int p = 0; p < 4; ++p) ffma2(acc2[p], wd3, hb[p].y);
        }
        float av[8];
        #pragma unroll
        for (int p = 0; p < 4; ++p) unpack2(acc2[p], av[2*p], av[2*p+1]);
        #pragma unroll
        for (int b = 0; b < 8; ++b) {
            float v = fmaf(av[b], mk[b], zr[b]);      // mask folded: m*(W@h)+Z
            float gv = (type == 2) ? tanh_fast(v) : sigm_fast(v);
            gbuf[j * 9 + b] = gv;
        }
        if (tid < 8) ms[nslot + tid] = 1.f - dn;      // mask for step t+1
        __syncthreads();

        // ---- Phase B1: c,h update (c masked here) ----
        #pragma unroll
        for (int it = 0; it < 2; ++it) {
            int idx = tid + it * 512;                 // 0..1023
            int b = idx >> 7, u = idx & 127;
            float m = ms[slot + b];
            int gbase = u * 9 + b;
            float iv = gbuf[gbase];
            float fv = gbuf[gbase + 128 * 9];
            float gg = gbuf[gbase + 256 * 9];
            float ov = gbuf[gbase + 384 * 9];
            float cv = fmaf(fv, cbuf[idx] * m, iv * gg);
            float hv = ov * tanh_fast(cv);
            cbuf[idx] = cv;
            hbuf[idx] = hv;
            // pair-interleaved copy for next step's matvec
            reinterpret_cast<float*>(hp)[(((b >> 1) << 7) + u) * 2 + (b & 1)] = hv;
        }
        __syncthreads();

        // ---- Phase B2: heads (18 logits + 1 value) ----
        if (tid < 8 * 19) {
            int b = tid / 19, a = tid - b * 19;
            float s0 = 0.f, s1 = 0.f;
            #pragma unroll 4
            for (int k8 = 0; k8 < 16; ++k8) {
                float4 w0 = *reinterpret_cast<const float4*>(&WaCs[a * 132 + k8 * 8]);
                float4 w1 = *reinterpret_cast<const float4*>(&WaCs[a * 132 + k8 * 8 + 4]);
                float4 hv0 = *reinterpret_cast<const float4*>(&hbuf[b * 128 + k8 * 8]);
                float4 hv1 = *reinterpret_cast<const float4*>(&hbuf[b * 128 + k8 * 8 + 4]);
                s0 = fmaf(w0.x, hv0.x, s0); s0 = fmaf(w0.y, hv0.y, s0);
                s0 = fmaf(w0.z, hv0.z, s0); s0 = fmaf(w0.w, hv0.w, s0);
                s1 = fmaf(w1.x, hv1.x, s1); s1 = fmaf(w1.y, hv1.y, s1);
                s1 = fmaf(w1.z, hv1.z, s1); s1 = fmaf(w1.w, hv1.w, s1);
            }
            out[((long)t * BB + gb0 + b) * 19 + a] = s0 + s1 + bac[a];
        }
        __syncthreads();
    }
}

// ---------------------------------------------------------------------------
// Host launcher
// ---------------------------------------------------------------------------
extern "C" void kernel_launch(void* const* d_in, const int* in_sizes, int n_in,
                              void* d_out, int out_size)
{
    const float* x    = (const float*)d_in[0];
    const float* done = (const float*)d_in[1];
    const float* h0   = (const float*)d_in[2];
    const float* c0   = (const float*)d_in[3];
    const float* W1   = (const float*)d_in[4];
    const float* b1   = (const float*)d_in[5];
    const float* W2   = (const float*)d_in[6];
    const float* b2   = (const float*)d_in[7];
    const float* W3   = (const float*)d_in[8];
    const float* b3   = (const float*)d_in[9];
    const float* Wih  = (const float*)d_in[10];
    const float* Whh  = (const float*)d_in[11];
    const float* bih  = (const float*)d_in[12];
    const float* bhh  = (const float*)d_in[13];
    const float* Wa   = (const float*)d_in[14];
    const float* ba   = (const float*)d_in[15];
    const float* Wc   = (const float*)d_in[16];
    const float* bc   = (const float*)d_in[17];
    float* out = (float*)d_out;

    float *h1p, *h2p, *h3p, *Zp;
    cudaGetSymbolAddress((void**)&h1p, g_h1);
    cudaGetSymbolAddress((void**)&h2p, g_h2);
    cudaGetSymbolAddress((void**)&h3p, g_h3);
    cudaGetSymbolAddress((void**)&Zp,  g_Z);

    const int S_128_128 = (128 * 68 + 128 * 132) * 4;  // 102400
    const int S_128_32  = (128 * 68 + 128 * 36)  * 4;  //  53248
    const int S_32_128  = (32  * 68 + 32  * 132) * 4;  //  25600

    cudaFuncSetAttribute(gemm_kernel<128, 128, true>,
                         cudaFuncAttributeMaxDynamicSharedMemorySize, S_128_128);
    cudaFuncSetAttribute(gemm_kernel<128, 128, false>,
                         cudaFuncAttributeMaxDynamicSharedMemorySize, S_128_128);
    cudaFuncSetAttribute(gemm_kernel<128, 32, true>,
                         cudaFuncAttributeMaxDynamicSharedMemorySize, S_128_32);
    cudaFuncSetAttribute(gemm_kernel<32, 128, true>,
                         cudaFuncAttributeMaxDynamicSharedMemorySize, S_32_128);
    cudaFuncSetAttribute(lstm_kernel,
                         cudaFuncAttributeMaxDynamicSharedMemorySize, SMEM_LSTM);

    const int NT_ROW = MROWS / 64;  // 4096 row tiles

    // Encoder (f32x2 SIMT)
    gemm_kernel<128, 128, true><<<dim3(NT_ROW, 1), 256, S_128_128>>>(
        x,   W1, b1, nullptr, h1p, 128);
    gemm_kernel<128, 32, true><<<dim3(NT_ROW, 1), 256, S_128_32>>>(
        h1p, W2, b2, nullptr, h2p, 32);
    gemm_kernel<32, 128, true><<<dim3(NT_ROW, 1), 256, S_32_128>>>(
        h2p, W3, b3, nullptr, h3p, 128);
    // Input projection: Z = hid @ Wih^T + bih + bhh   (N = 512, 4 col tiles)
    gemm_kernel<128, 128, false><<<dim3(NT_ROW, 4), 256, S_128_128>>>(
        h3p, Wih, bih, bhh, Zp, 512);

    // Recurrence + heads (f32x2, 8 lanes/CTA)
    lstm_kernel<<<128, 512, SMEM_LSTM>>>(
        Zp, done, h0, c0, Whh, Wa, ba, Wc, bc, out);
}